// round 2
// baseline (speedup 1.0000x reference)
#include <cuda_runtime.h>

// Fused Swin shifted-window attention, one window (64 tokens x 96 ch) per CTA.
// B=1, C=96, H=W=512, ws=8, heads=6, hd=16, shift=4. 4096 windows.
//
// Pipeline per block:
//   1) gather rolled input window into smem (the reference's raw-reshape+roll
//      is a flat shift src = f + 4*(W*C) + 4*C with two wrap corrections)
//   2) QKV = X @ Wqkv^T + b   (register-tiled 8x9 per thread, W in smem)
//   3) attention per (head,row) task with score matrix in smem, layout
//      s[m][h*64+n] so all lane accesses are stride-1 (conflict-free)
//   4) proj = O @ Wproj^T + b (register-tiled 8x3)
//   5) scatter to output (window_reverse; reference does NOT un-roll)

#define TPB 256

__global__ void __launch_bounds__(TPB, 1)
swin_fused_kernel(const float* __restrict__ x,
                  const float* __restrict__ rel_table,   // (225, 6)
                  const float* __restrict__ w_qkv,       // (288, 96)
                  const float* __restrict__ b_qkv,       // (288)
                  const float* __restrict__ w_proj,      // (96, 96)
                  const float* __restrict__ b_proj,      // (96)
                  float* __restrict__ out)
{
    constexpr int CH   = 96;
    constexpr int IMG  = 512;
    constexpr int HWSZ = IMG * IMG;      // 262144
    constexpr int CHW  = CH * HWSZ;      // 25165824
    constexpr int WC   = IMG * CH;       // 49152
    constexpr int ROLLOFF = 4 * WC + 4 * CH;  // 196992
    constexpr int XS_STR = 100;          // 64 x 100 input / attn-out tile
    constexpr int QK_STR = 292;          // 64 x 292 qkv tile (cols 0..287)
    constexpr int SC_STR = 392;          // 64 x 392 score tile (cols = h*64+n)
    constexpr int W_STR  = 97;           // padded weight rows

    extern __shared__ float sm[];
    float* xs  = sm;                     // 6400 floats
    float* qk  = sm + 6400;              // 18688 floats
    float* wsm = sm + 6400 + 18688;      // 27936 floats (aliased as scores)
    float* sc  = wsm;
    float* ts  = wsm + 27936;            // 1350 floats (bias table)

    const int tid = threadIdx.x;
    const int hb  = blockIdx.x >> 6;
    const int wb  = blockIdx.x & 63;

    // ---------------- phase 0: loads ----------------
    for (int i = tid; i < 225 * 6; i += TPB) ts[i] = rel_table[i];
    for (int i = tid; i < 288 * 96; i += TPB) {
        int o = i / 96, k = i % 96;
        wsm[o * W_STR + k] = w_qkv[i];
    }
    // gather rolled window: chunk = (channel, window-row), 8 contiguous floats
    for (int ch = tid; ch < 96 * 8; ch += TPB) {
        int c = ch >> 3, i = ch & 7;
        int f = c * HWSZ + (hb * 8 + i) * IMG + wb * 8;
        int hh = f / WC;                 // reinterpreted H coord
        int ww = (f / CH) & 511;         // reinterpreted W coord
        int src = f + ROLLOFF;
        if (hh >= IMG - 4) src -= CHW;
        if (ww >= IMG - 4) src -= WC;
        float4 v0 = *(const float4*)(x + src);
        float4 v1 = *(const float4*)(x + src + 4);
        float* d = xs + (i * 8) * XS_STR + c;   // tokens i*8+j, channel c
        d[0 * XS_STR] = v0.x; d[1 * XS_STR] = v0.y;
        d[2 * XS_STR] = v0.z; d[3 * XS_STR] = v0.w;
        d[4 * XS_STR] = v1.x; d[5 * XS_STR] = v1.y;
        d[6 * XS_STR] = v1.z; d[7 * XS_STR] = v1.w;
    }
    __syncthreads();

    // ---------------- phase 1: QKV GEMM (64x288, K=96) ----------------
    {
        const int tx = tid & 31, ty = tid >> 5;
        float acc[8][9];
        #pragma unroll
        for (int r = 0; r < 8; r++)
            #pragma unroll
            for (int j = 0; j < 9; j++) acc[r][j] = 0.f;

        for (int k = 0; k < 96; k++) {
            float a[8], b[9];
            #pragma unroll
            for (int r = 0; r < 8; r++) a[r] = xs[(ty * 8 + r) * XS_STR + k];
            #pragma unroll
            for (int j = 0; j < 9; j++) b[j] = wsm[(tx + 32 * j) * W_STR + k];
            #pragma unroll
            for (int r = 0; r < 8; r++)
                #pragma unroll
                for (int j = 0; j < 9; j++)
                    acc[r][j] = fmaf(a[r], b[j], acc[r][j]);
        }
        #pragma unroll
        for (int j = 0; j < 9; j++) {
            int col = tx + 32 * j;
            float bb = b_qkv[col];
            #pragma unroll
            for (int r = 0; r < 8; r++)
                qk[(ty * 8 + r) * QK_STR + col] = acc[r][j] + bb;
        }
    }
    __syncthreads();

    // ---------------- phase 2: attention ----------------
    {
        const bool hl = (hb == 63), wl = (wb == 63);
        for (int task = tid; task < 6 * 64; task += TPB) {
            const int h = task >> 6, n = task & 63;
            const int col = task;                   // h*64 + n
            const float4* qp = (const float4*)(qk + n * QK_STR + h * 16);
            const float4 q0 = qp[0], q1 = qp[1], q2 = qp[2], q3 = qp[3];
            const int yi = n >> 3, xi = n & 7;
            const int cn = (hl ? (yi < 4 ? 1 : 2) : 0) * 3
                         + (wl ? (xi < 4 ? 1 : 2) : 0);

            // scores + bias + mask
            for (int m = 0; m < 64; m++) {
                const float4* kp = (const float4*)(qk + m * QK_STR + 96 + h * 16);
                float4 k0 = kp[0], k1 = kp[1], k2 = kp[2], k3 = kp[3];
                float d = q0.x * k0.x + q0.y * k0.y + q0.z * k0.z + q0.w * k0.w
                        + q1.x * k1.x + q1.y * k1.y + q1.z * k1.z + q1.w * k1.w
                        + q2.x * k2.x + q2.y * k2.y + q2.z * k2.z + q2.w * k2.w
                        + q3.x * k3.x + q3.y * k3.y + q3.z * k3.z + q3.w * k3.w;
                const int ym = m >> 3, xm = m & 7;
                const int idx = (yi - ym + 7) * 15 + (xi - xm + 7);
                float v = d * 0.25f + ts[idx * 6 + h];
                const int cm = (hl ? (ym < 4 ? 1 : 2) : 0) * 3
                             + (wl ? (xm < 4 ? 1 : 2) : 0);
                if (cn != cm) v -= 100.0f;
                sc[m * SC_STR + col] = v;
            }
            // softmax over m (same-thread column: no sync needed)
            float mx = -1e30f;
            for (int m = 0; m < 64; m++) mx = fmaxf(mx, sc[m * SC_STR + col]);
            float sum = 0.f;
            for (int m = 0; m < 64; m++) {
                float e = __expf(sc[m * SC_STR + col] - mx);
                sc[m * SC_STR + col] = e;
                sum += e;
            }
            const float inv = 1.0f / sum;
            // attn @ V
            float4 o0 = {0, 0, 0, 0}, o1 = {0, 0, 0, 0},
                   o2 = {0, 0, 0, 0}, o3 = {0, 0, 0, 0};
            for (int m = 0; m < 64; m++) {
                const float p = sc[m * SC_STR + col] * inv;
                const float4* vp = (const float4*)(qk + m * QK_STR + 192 + h * 16);
                float4 v0 = vp[0], v1 = vp[1], v2 = vp[2], v3 = vp[3];
                o0.x = fmaf(p, v0.x, o0.x); o0.y = fmaf(p, v0.y, o0.y);
                o0.z = fmaf(p, v0.z, o0.z); o0.w = fmaf(p, v0.w, o0.w);
                o1.x = fmaf(p, v1.x, o1.x); o1.y = fmaf(p, v1.y, o1.y);
                o1.z = fmaf(p, v1.z, o1.z); o1.w = fmaf(p, v1.w, o1.w);
                o2.x = fmaf(p, v2.x, o2.x); o2.y = fmaf(p, v2.y, o2.y);
                o2.z = fmaf(p, v2.z, o2.z); o2.w = fmaf(p, v2.w, o2.w);
                o3.x = fmaf(p, v3.x, o3.x); o3.y = fmaf(p, v3.y, o3.y);
                o3.z = fmaf(p, v3.z, o3.z); o3.w = fmaf(p, v3.w, o3.w);
            }
            float4* op = (float4*)(xs + n * XS_STR + h * 16);
            op[0] = o0; op[1] = o1; op[2] = o2; op[3] = o3;
        }
    }
    __syncthreads();

    // ---------------- phase 3: load proj weights (overwrites scores) ----
    for (int i = tid; i < 96 * 96; i += TPB) {
        int o = i / 96, k = i % 96;
        wsm[o * W_STR + k] = w_proj[i];
    }
    __syncthreads();

    // ---------------- phase 4: proj GEMM (64x96, K=96) ----------------
    {
        const int tx = tid & 31, ty = tid >> 5;
        float acc[8][3];
        #pragma unroll
        for (int r = 0; r < 8; r++)
            #pragma unroll
            for (int j = 0; j < 3; j++) acc[r][j] = 0.f;

        for (int k = 0; k < 96; k++) {
            float a[8], b[3];
            #pragma unroll
            for (int r = 0; r < 8; r++) a[r] = xs[(ty * 8 + r) * XS_STR + k];
            #pragma unroll
            for (int j = 0; j < 3; j++) b[j] = wsm[(tx + 32 * j) * W_STR + k];
            #pragma unroll
            for (int r = 0; r < 8; r++)
                #pragma unroll
                for (int j = 0; j < 3; j++)
                    acc[r][j] = fmaf(a[r], b[j], acc[r][j]);
        }
        #pragma unroll
        for (int j = 0; j < 3; j++) {
            int col = tx + 32 * j;
            float bb = b_proj[col];
            #pragma unroll
            for (int r = 0; r < 8; r++)
                qk[(ty * 8 + r) * QK_STR + col] = acc[r][j] + bb;
        }
    }
    __syncthreads();

    // ---------------- phase 5: scatter to output ----------------
    for (int ch = tid; ch < 96 * 8; ch += TPB) {
        int c = ch >> 3, i = ch & 7;
        const float* s0 = qk + (i * 8) * QK_STR + c;
        float4 a, b;
        a.x = s0[0 * QK_STR]; a.y = s0[1 * QK_STR];
        a.z = s0[2 * QK_STR]; a.w = s0[3 * QK_STR];
        b.x = s0[4 * QK_STR]; b.y = s0[5 * QK_STR];
        b.z = s0[6 * QK_STR]; b.w = s0[7 * QK_STR];
        int dst = c * HWSZ + (hb * 8 + i) * IMG + wb * 8;
        *(float4*)(out + dst) = a;
        *(float4*)(out + dst + 4) = b;
    }
}

extern "C" void kernel_launch(void* const* d_in, const int* in_sizes, int n_in,
                              void* d_out, int out_size)
{
    const float* x         = (const float*)d_in[0];
    const float* rel_table = (const float*)d_in[1];
    const float* w_qkv     = (const float*)d_in[2];
    const float* b_qkv     = (const float*)d_in[3];
    const float* w_proj    = (const float*)d_in[4];
    const float* b_proj    = (const float*)d_in[5];
    float* out = (float*)d_out;

    constexpr int SMEM_BYTES = (6400 + 18688 + 27936 + 1350) * 4;  // 217496
    cudaFuncSetAttribute(swin_fused_kernel,
                         cudaFuncAttributeMaxDynamicSharedMemorySize, SMEM_BYTES);

    swin_fused_kernel<<<4096, TPB, SMEM_BYTES>>>(
        x, rel_table, w_qkv, b_qkv, w_proj, b_proj, out);
}

// round 3
// speedup vs baseline: 1.0782x; 1.0782x over previous
#include <cuda_runtime.h>

// Fused Swin shifted-window attention, one window (64 tokens x 96 ch) per CTA.
// R2: MUFU-free polynomial exp + packed fma.rn.f32x2 (FFMA2) GEMM inner loops.
// Input tile stored [channel][token] so register row-pairs load as 64-bit pairs.

#define TPB 256
typedef unsigned long long u64;

__device__ __forceinline__ u64 pack2(float lo, float hi) {
    u64 r; asm("mov.b64 %0, {%1, %2};" : "=l"(r) : "f"(lo), "f"(hi)); return r;
}
__device__ __forceinline__ float2 unpack2(u64 v) {
    float2 f; asm("mov.b64 {%0, %1}, %2;" : "=f"(f.x), "=f"(f.y) : "l"(v)); return f;
}
__device__ __forceinline__ u64 fma2(u64 a, u64 b, u64 c) {
    u64 d; asm("fma.rn.f32x2 %0, %1, %2, %3;" : "=l"(d) : "l"(a), "l"(b), "l"(c)); return d;
}
__device__ __forceinline__ u64 mul2(u64 a, u64 b) {
    u64 d; asm("mul.rn.f32x2 %0, %1, %2;" : "=l"(d) : "l"(a), "l"(b)); return d;
}
__device__ __forceinline__ u64 add2(u64 a, u64 b) {
    u64 d; asm("add.rn.f32x2 %0, %1, %2;" : "=l"(d) : "l"(a), "l"(b)); return d;
}

// exp(x) with x <= 0, FMA-pipe only (no MUFU). y = x*log2(e), magic-round,
// degree-5 poly for 2^f on [-0.5,0.5], exponent via bit add. rel err ~2e-6.
__device__ __forceinline__ float fast_exp(float y /* = x*log2e, pre-scaled */) {
    y = fmaxf(y, -120.0f);
    float t  = y + 12582912.0f;           // 1.5*2^23 magic: round-to-nearest
    float rf = t - 12582912.0f;
    int   k  = __float_as_int(t) - 0x4B400000;
    float f  = y - rf;                    // f in [-0.5, 0.5]
    float p  = 1.3333558e-3f;
    p = fmaf(p, f, 9.6181291e-3f);
    p = fmaf(p, f, 5.5504109e-2f);
    p = fmaf(p, f, 2.4022651e-1f);
    p = fmaf(p, f, 6.9314718e-1f);
    p = fmaf(p, f, 1.0f);
    return __int_as_float(__float_as_int(p) + (k << 23));
}

__global__ void __launch_bounds__(TPB, 1)
swin_fused_kernel(const float* __restrict__ x,
                  const float* __restrict__ rel_table,   // (225, 6)
                  const float* __restrict__ w_qkv,       // (288, 96)
                  const float* __restrict__ b_qkv,       // (288)
                  const float* __restrict__ w_proj,      // (96, 96)
                  const float* __restrict__ b_proj,      // (96)
                  float* __restrict__ out)
{
    constexpr int CH   = 96;
    constexpr int IMG  = 512;
    constexpr int HWSZ = IMG * IMG;
    constexpr int CHW  = CH * HWSZ;
    constexpr int WC   = IMG * CH;
    constexpr int ROLLOFF = 4 * WC + 4 * CH;
    constexpr int QK_STR = 292;          // 64 x 292 qkv tile
    constexpr int SC_STR = 392;          // 64 x 392 score tile
    constexpr int W_STR  = 97;
    constexpr float L2E  = 1.4426950408889634f;

    extern __shared__ float sm[];
    float* xs  = sm;                     // [96][64]  input / attn-out, 6144
    float* qk  = sm + 6144;              // 64 x 292 qkv (later proj out), 18688
    float* wsm = sm + 6144 + 18688;      // 27936 floats (weights / scores alias)
    float* sc  = wsm;
    float* ts  = wsm + 27936;            // 1350 floats bias table

    const int tid = threadIdx.x;
    const int hb  = blockIdx.x >> 6;
    const int wb  = blockIdx.x & 63;

    // ---------------- phase 0: loads ----------------
    for (int i = tid; i < 225 * 6; i += TPB) ts[i] = rel_table[i];
    for (int i = tid; i < 288 * 96; i += TPB) {
        int o = i / 96, k = i % 96;
        wsm[o * W_STR + k] = w_qkv[i];
    }
    // gather rolled window -> xs[channel][token] (two float4 smem stores)
    for (int ch = tid; ch < 96 * 8; ch += TPB) {
        int c = ch >> 3, i = ch & 7;
        int f = c * HWSZ + (hb * 8 + i) * IMG + wb * 8;
        int hh = f / WC;
        int ww = (f / CH) & 511;
        int src = f + ROLLOFF;
        if (hh >= IMG - 4) src -= CHW;
        if (ww >= IMG - 4) src -= WC;
        float4 v0 = *(const float4*)(x + src);
        float4 v1 = *(const float4*)(x + src + 4);
        *(float4*)(xs + c * 64 + i * 8)     = v0;
        *(float4*)(xs + c * 64 + i * 8 + 4) = v1;
    }
    __syncthreads();

    // ---------------- phase 1: QKV GEMM (64x288, K=96), FFMA2 ----------------
    {
        const int tx = tid & 31, ty = tid >> 5;
        u64 acc[4][9];
        #pragma unroll
        for (int r = 0; r < 4; r++)
            #pragma unroll
            for (int j = 0; j < 9; j++) acc[r][j] = 0ull;

        #pragma unroll 2
        for (int k = 0; k < 96; k++) {
            const u64* ap = (const u64*)(xs + k * 64 + ty * 8);  // broadcast
            u64 a0 = ap[0], a1 = ap[1], a2 = ap[2], a3 = ap[3];
            #pragma unroll
            for (int j = 0; j < 9; j++) {
                float bv = wsm[(tx + 32 * j) * W_STR + k];
                u64 bb = pack2(bv, bv);
                acc[0][j] = fma2(a0, bb, acc[0][j]);
                acc[1][j] = fma2(a1, bb, acc[1][j]);
                acc[2][j] = fma2(a2, bb, acc[2][j]);
                acc[3][j] = fma2(a3, bb, acc[3][j]);
            }
        }
        #pragma unroll
        for (int j = 0; j < 9; j++) {
            int col = tx + 32 * j;
            float bb = b_qkv[col];
            #pragma unroll
            for (int r = 0; r < 4; r++) {
                float2 u = unpack2(acc[r][j]);
                qk[(ty * 8 + 2 * r)     * QK_STR + col] = u.x + bb;
                qk[(ty * 8 + 2 * r + 1) * QK_STR + col] = u.y + bb;
            }
        }
    }
    __syncthreads();

    // ---------------- phase 2: attention ----------------
    {
        const bool hl = (hb == 63), wl = (wb == 63);
        for (int task = tid; task < 6 * 64; task += TPB) {
            const int h = task >> 6, n = task & 63;
            const int col = task;
            const u64* qp = (const u64*)(qk + n * QK_STR + h * 16);
            u64 q2[8];
            #pragma unroll
            for (int i = 0; i < 8; i++) q2[i] = qp[i];
            const int yi = n >> 3, xi = n & 7;
            const int cn = (hl ? (yi < 4 ? 1 : 2) : 0) * 3
                         + (wl ? (xi < 4 ? 1 : 2) : 0);

            // scores + bias + mask (scaled by log2e for the exp stage)
            #pragma unroll 2
            for (int m = 0; m < 64; m++) {
                const u64* kp = (const u64*)(qk + m * QK_STR + 96 + h * 16);
                u64 da = mul2(q2[0], kp[0]);
                u64 db = mul2(q2[1], kp[1]);
                da = fma2(q2[2], kp[2], da);
                db = fma2(q2[3], kp[3], db);
                da = fma2(q2[4], kp[4], da);
                db = fma2(q2[5], kp[5], db);
                da = fma2(q2[6], kp[6], da);
                db = fma2(q2[7], kp[7], db);
                float2 dd = unpack2(add2(da, db));
                float d = dd.x + dd.y;
                const int ym = m >> 3, xm = m & 7;
                const int idx = (yi - ym + 7) * 15 + (xi - xm + 7);
                float v = d * 0.25f + ts[idx * 6 + h];
                const int cm = (hl ? (ym < 4 ? 1 : 2) : 0) * 3
                             + (wl ? (xm < 4 ? 1 : 2) : 0);
                if (cn != cm) v -= 100.0f;
                sc[m * SC_STR + col] = v;
            }
            // softmax over m (same-thread column)
            float mx = -1e30f;
            #pragma unroll 8
            for (int m = 0; m < 64; m++) mx = fmaxf(mx, sc[m * SC_STR + col]);
            const float mxl = mx * L2E;
            float s0 = 0.f, s1 = 0.f;
            #pragma unroll 4
            for (int m = 0; m < 64; m += 2) {
                float e0 = fast_exp(fmaf(sc[m * SC_STR + col], L2E, -mxl));
                float e1 = fast_exp(fmaf(sc[(m + 1) * SC_STR + col], L2E, -mxl));
                sc[m * SC_STR + col] = e0;
                sc[(m + 1) * SC_STR + col] = e1;
                s0 += e0; s1 += e1;
            }
            const float inv = 1.0f / (s0 + s1);
            // attn @ V, FFMA2
            u64 o2[8];
            #pragma unroll
            for (int i = 0; i < 8; i++) o2[i] = 0ull;
            #pragma unroll 2
            for (int m = 0; m < 64; m++) {
                const float p = sc[m * SC_STR + col] * inv;
                const u64 pp = pack2(p, p);
                const u64* vp = (const u64*)(qk + m * QK_STR + 192 + h * 16);
                #pragma unroll
                for (int i = 0; i < 8; i++) o2[i] = fma2(pp, vp[i], o2[i]);
            }
            // store attn output to xs[channel][token]
            #pragma unroll
            for (int i = 0; i < 8; i++) {
                float2 u = unpack2(o2[i]);
                xs[(h * 16 + 2 * i)     * 64 + n] = u.x;
                xs[(h * 16 + 2 * i + 1) * 64 + n] = u.y;
            }
        }
    }
    __syncthreads();

    // ---------------- phase 3: load proj weights (overwrites scores) ----
    for (int i = tid; i < 96 * 96; i += TPB) {
        int o = i / 96, k = i % 96;
        wsm[o * W_STR + k] = w_proj[i];
    }
    __syncthreads();

    // ---------------- phase 4: proj GEMM (64x96, K=96), FFMA2 ----------------
    {
        const int tx = tid & 31, ty = tid >> 5;
        u64 acc[4][3];
        #pragma unroll
        for (int r = 0; r < 4; r++)
            #pragma unroll
            for (int j = 0; j < 3; j++) acc[r][j] = 0ull;

        #pragma unroll 2
        for (int k = 0; k < 96; k++) {
            const u64* ap = (const u64*)(xs + k * 64 + ty * 8);  // broadcast
            u64 a0 = ap[0], a1 = ap[1], a2 = ap[2], a3 = ap[3];
            #pragma unroll
            for (int j = 0; j < 3; j++) {
                float bv = wsm[(tx + 32 * j) * W_STR + k];
                u64 bb = pack2(bv, bv);
                acc[0][j] = fma2(a0, bb, acc[0][j]);
                acc[1][j] = fma2(a1, bb, acc[1][j]);
                acc[2][j] = fma2(a2, bb, acc[2][j]);
                acc[3][j] = fma2(a3, bb, acc[3][j]);
            }
        }
        #pragma unroll
        for (int j = 0; j < 3; j++) {
            int col = tx + 32 * j;
            float bb = b_proj[col];
            #pragma unroll
            for (int r = 0; r < 4; r++) {
                float2 u = unpack2(acc[r][j]);
                qk[(ty * 8 + 2 * r)     * QK_STR + col] = u.x + bb;
                qk[(ty * 8 + 2 * r + 1) * QK_STR + col] = u.y + bb;
            }
        }
    }
    __syncthreads();

    // ---------------- phase 5: scatter to output ----------------
    for (int ch = tid; ch < 96 * 8; ch += TPB) {
        int c = ch >> 3, i = ch & 7;
        const float* s0 = qk + (i * 8) * QK_STR + c;
        float4 a, b;
        a.x = s0[0 * QK_STR]; a.y = s0[1 * QK_STR];
        a.z = s0[2 * QK_STR]; a.w = s0[3 * QK_STR];
        b.x = s0[4 * QK_STR]; b.y = s0[5 * QK_STR];
        b.z = s0[6 * QK_STR]; b.w = s0[7 * QK_STR];
        int dst = c * HWSZ + (hb * 8 + i) * IMG + wb * 8;
        *(float4*)(out + dst) = a;
        *(float4*)(out + dst + 4) = b;
    }
}

extern "C" void kernel_launch(void* const* d_in, const int* in_sizes, int n_in,
                              void* d_out, int out_size)
{
    const float* x         = (const float*)d_in[0];
    const float* rel_table = (const float*)d_in[1];
    const float* w_qkv     = (const float*)d_in[2];
    const float* b_qkv     = (const float*)d_in[3];
    const float* w_proj    = (const float*)d_in[4];
    const float* b_proj    = (const float*)d_in[5];
    float* out = (float*)d_out;

    constexpr int SMEM_BYTES = (6144 + 18688 + 27936 + 1350) * 4;  // 216472
    cudaFuncSetAttribute(swin_fused_kernel,
                         cudaFuncAttributeMaxDynamicSharedMemorySize, SMEM_BYTES);

    swin_fused_kernel<<<4096, TPB, SMEM_BYTES>>>(
        x, rel_table, w_qkv, b_qkv, w_proj, b_proj, out);
}

// round 6
// speedup vs baseline: 1.1612x; 1.0770x over previous
#include <cuda_runtime.h>

// Fused Swin shifted-window attention, one window (64 tokens x 96 ch) per CTA.
// R3: 512 threads/CTA (16 warps -> 4 warps/SMSP) to fix issue-limited execution.
// FFMA2 packed math everywhere, MUFU-free exp, softmax max fused into score pass.

#define TPB 512
typedef unsigned long long u64;

__device__ __forceinline__ u64 pack2(float lo, float hi) {
    u64 r; asm("mov.b64 %0, {%1, %2};" : "=l"(r) : "f"(lo), "f"(hi)); return r;
}
__device__ __forceinline__ float2 unpack2(u64 v) {
    float2 f; asm("mov.b64 {%0, %1}, %2;" : "=f"(f.x), "=f"(f.y) : "l"(v)); return f;
}
__device__ __forceinline__ u64 fma2(u64 a, u64 b, u64 c) {
    u64 d; asm("fma.rn.f32x2 %0, %1, %2, %3;" : "=l"(d) : "l"(a), "l"(b), "l"(c)); return d;
}
__device__ __forceinline__ u64 mul2(u64 a, u64 b) {
    u64 d; asm("mul.rn.f32x2 %0, %1, %2;" : "=l"(d) : "l"(a), "l"(b)); return d;
}
__device__ __forceinline__ u64 add2(u64 a, u64 b) {
    u64 d; asm("add.rn.f32x2 %0, %1, %2;" : "=l"(d) : "l"(a), "l"(b)); return d;
}

// exp(x), FMA-pipe only. Input y = x*log2(e). rel err ~2e-6.
__device__ __forceinline__ float fast_exp(float y) {
    y = fmaxf(y, -120.0f);
    float t  = y + 12582912.0f;           // 1.5*2^23 magic round
    float rf = t - 12582912.0f;
    int   k  = __float_as_int(t) - 0x4B400000;
    float f  = y - rf;
    float p  = 1.3333558e-3f;
    p = fmaf(p, f, 9.6181291e-3f);
    p = fmaf(p, f, 5.5504109e-2f);
    p = fmaf(p, f, 2.4022651e-1f);
    p = fmaf(p, f, 6.9314718e-1f);
    p = fmaf(p, f, 1.0f);
    return __int_as_float(__float_as_int(p) + (k << 23));
}

__global__ void __launch_bounds__(TPB, 1)
swin_fused_kernel(const float* __restrict__ x,
                  const float* __restrict__ rel_table,   // (225, 6)
                  const float* __restrict__ w_qkv,       // (288, 96)
                  const float* __restrict__ b_qkv,       // (288)
                  const float* __restrict__ w_proj,      // (96, 96)
                  const float* __restrict__ b_proj,      // (96)
                  float* __restrict__ out)
{
    constexpr int CH   = 96;
    constexpr int IMG  = 512;
    constexpr int HWSZ = IMG * IMG;
    constexpr int CHW  = CH * HWSZ;
    constexpr int WC   = IMG * CH;
    constexpr int ROLLOFF = 4 * WC + 4 * CH;
    constexpr int QK_STR = 292;          // 64 x 292 qkv tile
    constexpr int SC_STR = 392;          // 64 x 392 score tile
    constexpr int W_STR  = 97;
    constexpr float L2E  = 1.4426950408889634f;

    extern __shared__ float sm[];
    float* xs  = sm;                     // [96][64] input / attn-out, 6144
    float* qk  = sm + 6144;              // 64 x 292 qkv (later proj out), 18688
    float* wsm = sm + 6144 + 18688;      // 27936 floats (weights / scores alias)
    float* sc  = wsm;
    float* ts  = wsm + 27936;            // 1350 floats bias table

    const int tid = threadIdx.x;
    const int hb  = blockIdx.x >> 6;
    const int wb  = blockIdx.x & 63;

    // ---------------- phase 0: loads ----------------
    for (int i = tid; i < 225 * 6; i += TPB) ts[i] = rel_table[i];
    for (int i = tid; i < 288 * 96; i += TPB) {
        int o = i / 96, k = i % 96;
        wsm[o * W_STR + k] = w_qkv[i];
    }
    // gather rolled window -> xs[channel][token]
    for (int ch = tid; ch < 96 * 8; ch += TPB) {
        int c = ch >> 3, i = ch & 7;
        int f = c * HWSZ + (hb * 8 + i) * IMG + wb * 8;
        int hh = f / WC;
        int ww = (f / CH) & 511;
        int src = f + ROLLOFF;
        if (hh >= IMG - 4) src -= CHW;
        if (ww >= IMG - 4) src -= WC;
        float4 v0 = *(const float4*)(x + src);
        float4 v1 = *(const float4*)(x + src + 4);
        *(float4*)(xs + c * 64 + i * 8)     = v0;
        *(float4*)(xs + c * 64 + i * 8 + 4) = v1;
    }
    __syncthreads();

    // ------- phase 1: QKV GEMM (64x288, K=96), 16 warps x (4 rows, 9 cols) ----
    {
        const int tx = tid & 31, wd = tid >> 5;   // wd 0..15 -> rows wd*4..wd*4+3
        u64 acc[2][9];
        #pragma unroll
        for (int r = 0; r < 2; r++)
            #pragma unroll
            for (int j = 0; j < 9; j++) acc[r][j] = 0ull;

        #pragma unroll 2
        for (int k = 0; k < 96; k++) {
            const u64* ap = (const u64*)(xs + k * 64 + wd * 4);  // broadcast
            u64 a0 = ap[0], a1 = ap[1];
            #pragma unroll
            for (int j = 0; j < 9; j++) {
                float bv = wsm[(tx + 32 * j) * W_STR + k];
                u64 bb = pack2(bv, bv);
                acc[0][j] = fma2(a0, bb, acc[0][j]);
                acc[1][j] = fma2(a1, bb, acc[1][j]);
            }
        }
        #pragma unroll
        for (int j = 0; j < 9; j++) {
            int col = tx + 32 * j;
            float bb = b_qkv[col];
            #pragma unroll
            for (int r = 0; r < 2; r++) {
                float2 u = unpack2(acc[r][j]);
                qk[(wd * 4 + 2 * r)     * QK_STR + col] = u.x + bb;
                qk[(wd * 4 + 2 * r + 1) * QK_STR + col] = u.y + bb;
            }
        }
    }
    __syncthreads();

    // ---------------- phase 2: attention (384 tasks, threads 0..383) ---------
    if (tid < 6 * 64) {
        const bool hl = (hb == 63), wl = (wb == 63);
        const int task = tid;
        const int h = task >> 6, n = task & 63;
        const int col = task;
        const u64* qp = (const u64*)(qk + n * QK_STR + h * 16);
        u64 q2[8];
        #pragma unroll
        for (int i = 0; i < 8; i++) q2[i] = qp[i];
        const int yi = n >> 3, xi = n & 7;
        const int cn = (hl ? (yi < 4 ? 1 : 2) : 0) * 3
                     + (wl ? (xi < 4 ? 1 : 2) : 0);

        // scores + bias + mask, fused running max
        float mx = -1e30f;
        #pragma unroll 2
        for (int m = 0; m < 64; m++) {
            const u64* kp = (const u64*)(qk + m * QK_STR + 96 + h * 16);
            u64 da = mul2(q2[0], kp[0]);
            u64 db = mul2(q2[1], kp[1]);
            da = fma2(q2[2], kp[2], da);
            db = fma2(q2[3], kp[3], db);
            da = fma2(q2[4], kp[4], da);
            db = fma2(q2[5], kp[5], db);
            da = fma2(q2[6], kp[6], da);
            db = fma2(q2[7], kp[7], db);
            float2 dd = unpack2(add2(da, db));
            float d = dd.x + dd.y;
            const int ym = m >> 3, xm = m & 7;
            const int idx = (yi - ym + 7) * 15 + (xi - xm + 7);
            float v = d * 0.25f + ts[idx * 6 + h];
            const int cm = (hl ? (ym < 4 ? 1 : 2) : 0) * 3
                         + (wl ? (xm < 4 ? 1 : 2) : 0);
            if (cn != cm) v -= 100.0f;
            sc[m * SC_STR + col] = v;
            mx = fmaxf(mx, v);
        }
        // exp + sum
        const float mxl = mx * L2E;
        float s0 = 0.f, s1 = 0.f;
        #pragma unroll 4
        for (int m = 0; m < 64; m += 2) {
            float e0 = fast_exp(fmaf(sc[m * SC_STR + col], L2E, -mxl));
            float e1 = fast_exp(fmaf(sc[(m + 1) * SC_STR + col], L2E, -mxl));
            sc[m * SC_STR + col] = e0;
            sc[(m + 1) * SC_STR + col] = e1;
            s0 += e0; s1 += e1;
        }
        const float inv = 1.0f / (s0 + s1);
        // attn @ V, FFMA2
        u64 o2[8];
        #pragma unroll
        for (int i = 0; i < 8; i++) o2[i] = 0ull;
        #pragma unroll 2
        for (int m = 0; m < 64; m++) {
            const float p = sc[m * SC_STR + col] * inv;
            const u64 pp = pack2(p, p);
            const u64* vp = (const u64*)(qk + m * QK_STR + 192 + h * 16);
            #pragma unroll
            for (int i = 0; i < 8; i++) o2[i] = fma2(pp, vp[i], o2[i]);
        }
        // store attn output to xs[channel][token]
        #pragma unroll
        for (int i = 0; i < 8; i++) {
            float2 u = unpack2(o2[i]);
            xs[(h * 16 + 2 * i)     * 64 + n] = u.x;
            xs[(h * 16 + 2 * i + 1) * 64 + n] = u.y;
        }
    }
    __syncthreads();

    // ---------------- phase 3: load proj weights (overwrites scores) --------
    for (int i = tid; i < 96 * 96; i += TPB) {
        int o = i / 96, k = i % 96;
        wsm[o * W_STR + k] = w_proj[i];
    }
    __syncthreads();

    // ------- phase 4: proj GEMM (64x96, K=96), 16 warps x (4 rows, 3 cols) ---
    {
        const int tx = tid & 31, wd = tid >> 5;
        u64 acc[2][3];
        #pragma unroll
        for (int r = 0; r < 2; r++)
            #pragma unroll
            for (int j = 0; j < 3; j++) acc[r][j] = 0ull;

        #pragma unroll 4
        for (int k = 0; k < 96; k++) {
            const u64* ap = (const u64*)(xs + k * 64 + wd * 4);  // broadcast
            u64 a0 = ap[0], a1 = ap[1];
            #pragma unroll
            for (int j = 0; j < 3; j++) {
                float bv = wsm[(tx + 32 * j) * W_STR + k];
                u64 bb = pack2(bv, bv);
                acc[0][j] = fma2(a0, bb, acc[0][j]);
                acc[1][j] = fma2(a1, bb, acc[1][j]);
            }
        }
        #pragma unroll
        for (int j = 0; j < 3; j++) {
            int col = tx + 32 * j;
            float bb = b_proj[col];
            #pragma unroll
            for (int r = 0; r < 2; r++) {
                float2 u = unpack2(acc[r][j]);
                qk[(wd * 4 + 2 * r)     * QK_STR + col] = u.x + bb;
                qk[(wd * 4 + 2 * r + 1) * QK_STR + col] = u.y + bb;
            }
        }
    }
    __syncthreads();

    // ---------------- phase 5: scatter to output ----------------
    for (int ch = tid; ch < 96 * 8; ch += TPB) {
        int c = ch >> 3, i = ch & 7;
        const float* s0 = qk + (i * 8) * QK_STR + c;
        float4 a, b;
        a.x = s0[0 * QK_STR]; a.y = s0[1 * QK_STR];
        a.z = s0[2 * QK_STR]; a.w = s0[3 * QK_STR];
        b.x = s0[4 * QK_STR]; b.y = s0[5 * QK_STR];
        b.z = s0[6 * QK_STR]; b.w = s0[7 * QK_STR];
        int dst = c * HWSZ + (hb * 8 + i) * IMG + wb * 8;
        *(float4*)(out + dst) = a;
        *(float4*)(out + dst + 4) = b;
    }
}

extern "C" void kernel_launch(void* const* d_in, const int* in_sizes, int n_in,
                              void* d_out, int out_size)
{
    const float* x         = (const float*)d_in[0];
    const float* rel_table = (const float*)d_in[1];
    const float* w_qkv     = (const float*)d_in[2];
    const float* b_qkv     = (const float*)d_in[3];
    const float* w_proj    = (const float*)d_in[4];
    const float* b_proj    = (const float*)d_in[5];
    float* out = (float*)d_out;

    constexpr int SMEM_BYTES = (6144 + 18688 + 27936 + 1350) * 4;  // 216472
    cudaFuncSetAttribute(swin_fused_kernel,
                         cudaFuncAttributeMaxDynamicSharedMemorySize, SMEM_BYTES);

    swin_fused_kernel<<<4096, TPB, SMEM_BYTES>>>(
        x, rel_table, w_qkv, b_qkv, w_proj, b_proj, out);
}

// round 8
// speedup vs baseline: 1.3515x; 1.1639x over previous
#include <cuda_runtime.h>

// Fused Swin shifted-window attention, one window (64 tokens x 96 ch) per CTA.
// R6: crossbar-traffic reduction. LDS.128 loads in attention, 2-k-step GEMMs
// with LDS.64 weight reads (W_STR=98), exp+sum fused into the A*V pass.

#define TPB 512
typedef unsigned long long u64;

__device__ __forceinline__ u64 pack2(float lo, float hi) {
    u64 r; asm("mov.b64 %0, {%1, %2};" : "=l"(r) : "f"(lo), "f"(hi)); return r;
}
__device__ __forceinline__ float2 unpack2(u64 v) {
    float2 f; asm("mov.b64 {%0, %1}, %2;" : "=f"(f.x), "=f"(f.y) : "l"(v)); return f;
}
__device__ __forceinline__ u64 fma2(u64 a, u64 b, u64 c) {
    u64 d; asm("fma.rn.f32x2 %0, %1, %2, %3;" : "=l"(d) : "l"(a), "l"(b), "l"(c)); return d;
}
__device__ __forceinline__ u64 mul2(u64 a, u64 b) {
    u64 d; asm("mul.rn.f32x2 %0, %1, %2;" : "=l"(d) : "l"(a), "l"(b)); return d;
}
__device__ __forceinline__ u64 add2(u64 a, u64 b) {
    u64 d; asm("add.rn.f32x2 %0, %1, %2;" : "=l"(d) : "l"(a), "l"(b)); return d;
}
__device__ __forceinline__ void f4u(const float4 v, u64& lo, u64& hi) {
    lo = pack2(v.x, v.y); hi = pack2(v.z, v.w);
}

// exp(x), FMA-pipe only. Input y = x*log2(e). rel err ~2e-6.
__device__ __forceinline__ float fast_exp(float y) {
    y = fmaxf(y, -120.0f);
    float t  = y + 12582912.0f;           // 1.5*2^23 magic round
    float rf = t - 12582912.0f;
    int   k  = __float_as_int(t) - 0x4B400000;
    float f  = y - rf;
    float p  = 1.3333558e-3f;
    p = fmaf(p, f, 9.6181291e-3f);
    p = fmaf(p, f, 5.5504109e-2f);
    p = fmaf(p, f, 2.4022651e-1f);
    p = fmaf(p, f, 6.9314718e-1f);
    p = fmaf(p, f, 1.0f);
    return __int_as_float(__float_as_int(p) + (k << 23));
}

__global__ void __launch_bounds__(TPB, 1)
swin_fused_kernel(const float* __restrict__ x,
                  const float* __restrict__ rel_table,   // (225, 6)
                  const float* __restrict__ w_qkv,       // (288, 96)
                  const float* __restrict__ b_qkv,       // (288)
                  const float* __restrict__ w_proj,      // (96, 96)
                  const float* __restrict__ b_proj,      // (96)
                  float* __restrict__ out)
{
    constexpr int CH   = 96;
    constexpr int IMG  = 512;
    constexpr int HWSZ = IMG * IMG;
    constexpr int CHW  = CH * HWSZ;
    constexpr int WC   = IMG * CH;
    constexpr int ROLLOFF = 4 * WC + 4 * CH;
    constexpr int QK_STR = 292;          // 64 x 292 qkv tile (mult of 4)
    constexpr int SC_STR = 392;          // 64 x 392 score tile
    constexpr int W_STR  = 98;           // even: LDS.64 aligned, 2-way bank stride ok for .64
    constexpr float L2E  = 1.4426950408889634f;

    extern __shared__ float sm[];
    float* xs  = sm;                     // [96][64] input / attn-out, 6144
    float* qk  = sm + 6144;              // 64 x 292 qkv (later proj out), 18688
    float* wsm = sm + 6144 + 18688;      // 28224 floats (weights / scores alias)
    float* sc  = wsm;
    float* ts  = wsm + 28224;            // 1350 floats bias table

    const int tid = threadIdx.x;
    const int hb  = blockIdx.x >> 6;
    const int wb  = blockIdx.x & 63;

    // ---------------- phase 0: loads ----------------
    for (int i = tid; i < 225 * 6; i += TPB) ts[i] = rel_table[i];
    // w_qkv: 288x96, float4 LDG; rows are 24 float4 so a float4 never crosses a row
    for (int i4 = tid * 4; i4 < 288 * 96; i4 += TPB * 4) {
        float4 v = *(const float4*)(w_qkv + i4);
        int o = i4 / 96, k = i4 % 96;
        float* d = wsm + o * W_STR + k;
        d[0] = v.x; d[1] = v.y; d[2] = v.z; d[3] = v.w;
    }
    // gather rolled window -> xs[channel][token]
    for (int ch = tid; ch < 96 * 8; ch += TPB) {
        int c = ch >> 3, i = ch & 7;
        int f = c * HWSZ + (hb * 8 + i) * IMG + wb * 8;
        int hh = f / WC;
        int ww = (f / CH) & 511;
        int src = f + ROLLOFF;
        if (hh >= IMG - 4) src -= CHW;
        if (ww >= IMG - 4) src -= WC;
        float4 v0 = *(const float4*)(x + src);
        float4 v1 = *(const float4*)(x + src + 4);
        *(float4*)(xs + c * 64 + i * 8)     = v0;
        *(float4*)(xs + c * 64 + i * 8 + 4) = v1;
    }
    __syncthreads();

    // ------- phase 1: QKV GEMM (64x288, K=96), 2-k step, 16 warps ----------
    {
        const int tx = tid & 31, wd = tid >> 5;   // rows wd*4..wd*4+3
        u64 acc[2][9];
        #pragma unroll
        for (int r = 0; r < 2; r++)
            #pragma unroll
            for (int j = 0; j < 9; j++) acc[r][j] = 0ull;

        #pragma unroll 2
        for (int k = 0; k < 96; k += 2) {
            float4 av0 = *(const float4*)(xs + k * 64 + wd * 4);       // k
            float4 av1 = *(const float4*)(xs + (k + 1) * 64 + wd * 4); // k+1
            u64 a0lo, a0hi, a1lo, a1hi;
            f4u(av0, a0lo, a0hi);
            f4u(av1, a1lo, a1hi);
            #pragma unroll
            for (int j = 0; j < 9; j++) {
                float2 b = *(const float2*)(wsm + (tx + 32 * j) * W_STR + k);
                u64 b0 = pack2(b.x, b.x);
                u64 b1 = pack2(b.y, b.y);
                acc[0][j] = fma2(a0lo, b0, acc[0][j]);
                acc[1][j] = fma2(a0hi, b0, acc[1][j]);
                acc[0][j] = fma2(a1lo, b1, acc[0][j]);
                acc[1][j] = fma2(a1hi, b1, acc[1][j]);
            }
        }
        #pragma unroll
        for (int j = 0; j < 9; j++) {
            int col = tx + 32 * j;
            float bb = b_qkv[col];
            #pragma unroll
            for (int r = 0; r < 2; r++) {
                float2 u = unpack2(acc[r][j]);
                qk[(wd * 4 + 2 * r)     * QK_STR + col] = u.x + bb;
                qk[(wd * 4 + 2 * r + 1) * QK_STR + col] = u.y + bb;
            }
        }
    }
    __syncthreads();

    // ---------------- phase 2: attention (384 tasks, threads 0..383) ---------
    if (tid < 6 * 64) {
        const bool hl = (hb == 63), wl = (wb == 63);
        const int h = tid >> 6, n = tid & 63;
        const int col = tid;
        const float4* qp = (const float4*)(qk + n * QK_STR + h * 16);
        u64 q2[8];
        {
            float4 a = qp[0], b = qp[1], c = qp[2], d = qp[3];
            f4u(a, q2[0], q2[1]); f4u(b, q2[2], q2[3]);
            f4u(c, q2[4], q2[5]); f4u(d, q2[6], q2[7]);
        }
        const int yi = n >> 3, xi = n & 7;
        const int cn = (hl ? (yi < 4 ? 1 : 2) : 0) * 3
                     + (wl ? (xi < 4 ? 1 : 2) : 0);

        // pass 1: scores + bias + mask -> smem, running max
        float mx = -1e30f;
        #pragma unroll 2
        for (int m = 0; m < 64; m++) {
            const float4* kp = (const float4*)(qk + m * QK_STR + 96 + h * 16);
            float4 kv0 = kp[0], kv1 = kp[1], kv2 = kp[2], kv3 = kp[3];
            u64 k0, k1, k2, k3, k4, k5, k6, k7;
            f4u(kv0, k0, k1); f4u(kv1, k2, k3);
            f4u(kv2, k4, k5); f4u(kv3, k6, k7);
            u64 da = mul2(q2[0], k0);
            u64 db = mul2(q2[1], k1);
            da = fma2(q2[2], k2, da);
            db = fma2(q2[3], k3, db);
            da = fma2(q2[4], k4, da);
            db = fma2(q2[5], k5, db);
            da = fma2(q2[6], k6, da);
            db = fma2(q2[7], k7, db);
            float2 dd = unpack2(add2(da, db));
            float d = dd.x + dd.y;
            const int ym = m >> 3, xm = m & 7;
            const int idx = (yi - ym + 7) * 15 + (xi - xm + 7);
            float v = d * 0.25f + ts[idx * 6 + h];
            const int cm = (hl ? (ym < 4 ? 1 : 2) : 0) * 3
                         + (wl ? (xm < 4 ? 1 : 2) : 0);
            if (cn != cm) v -= 100.0f;
            sc[m * SC_STR + col] = v;
            mx = fmaxf(mx, v);
        }
        // pass 2: exp + sum + unnormalized A*V, fused
        const float mxl = mx * L2E;
        float s0 = 0.f, s1 = 0.f;
        u64 o2[8];
        #pragma unroll
        for (int i = 0; i < 8; i++) o2[i] = 0ull;
        #pragma unroll 2
        for (int m = 0; m < 64; m += 2) {
            float e0 = fast_exp(fmaf(sc[m * SC_STR + col], L2E, -mxl));
            float e1 = fast_exp(fmaf(sc[(m + 1) * SC_STR + col], L2E, -mxl));
            s0 += e0; s1 += e1;
            const u64 p0 = pack2(e0, e0);
            const u64 p1 = pack2(e1, e1);
            const float4* vp0 = (const float4*)(qk + m * QK_STR + 192 + h * 16);
            const float4* vp1 = (const float4*)(qk + (m + 1) * QK_STR + 192 + h * 16);
            float4 va = vp0[0], vb = vp0[1], vc = vp0[2], vd = vp0[3];
            u64 v0, v1, v2, v3, v4, v5, v6, v7;
            f4u(va, v0, v1); f4u(vb, v2, v3); f4u(vc, v4, v5); f4u(vd, v6, v7);
            o2[0] = fma2(p0, v0, o2[0]); o2[1] = fma2(p0, v1, o2[1]);
            o2[2] = fma2(p0, v2, o2[2]); o2[3] = fma2(p0, v3, o2[3]);
            o2[4] = fma2(p0, v4, o2[4]); o2[5] = fma2(p0, v5, o2[5]);
            o2[6] = fma2(p0, v6, o2[6]); o2[7] = fma2(p0, v7, o2[7]);
            va = vp1[0]; vb = vp1[1]; vc = vp1[2]; vd = vp1[3];
            f4u(va, v0, v1); f4u(vb, v2, v3); f4u(vc, v4, v5); f4u(vd, v6, v7);
            o2[0] = fma2(p1, v0, o2[0]); o2[1] = fma2(p1, v1, o2[1]);
            o2[2] = fma2(p1, v2, o2[2]); o2[3] = fma2(p1, v3, o2[3]);
            o2[4] = fma2(p1, v4, o2[4]); o2[5] = fma2(p1, v5, o2[5]);
            o2[6] = fma2(p1, v6, o2[6]); o2[7] = fma2(p1, v7, o2[7]);
        }
        const float inv = 1.0f / (s0 + s1);
        // store normalized attn output to xs[channel][token]
        #pragma unroll
        for (int i = 0; i < 8; i++) {
            float2 u = unpack2(o2[i]);
            xs[(h * 16 + 2 * i)     * 64 + n] = u.x * inv;
            xs[(h * 16 + 2 * i + 1) * 64 + n] = u.y * inv;
        }
    }
    __syncthreads();

    // ---------------- phase 3: load proj weights (overwrites scores) --------
    for (int i4 = tid * 4; i4 < 96 * 96; i4 += TPB * 4) {
        float4 v = *(const float4*)(w_proj + i4);
        int o = i4 / 96, k = i4 % 96;
        float* d = wsm + o * W_STR + k;
        d[0] = v.x; d[1] = v.y; d[2] = v.z; d[3] = v.w;
    }
    __syncthreads();

    // ------- phase 4: proj GEMM (64x96, K=96), 2-k step, 16 warps -----------
    {
        const int tx = tid & 31, wd = tid >> 5;
        u64 acc[2][3];
        #pragma unroll
        for (int r = 0; r < 2; r++)
            #pragma unroll
            for (int j = 0; j < 3; j++) acc[r][j] = 0ull;

        #pragma unroll 2
        for (int k = 0; k < 96; k += 2) {
            float4 av0 = *(const float4*)(xs + k * 64 + wd * 4);
            float4 av1 = *(const float4*)(xs + (k + 1) * 64 + wd * 4);
            u64 a0lo, a0hi, a1lo, a1hi;
            f4u(av0, a0lo, a0hi);
            f4u(av1, a1lo, a1hi);
            #pragma unroll
            for (int j = 0; j < 3; j++) {
                float2 b = *(const float2*)(wsm + (tx + 32 * j) * W_STR + k);
                u64 b0 = pack2(b.x, b.x);
                u64 b1 = pack2(b.y, b.y);
                acc[0][j] = fma2(a0lo, b0, acc[0][j]);
                acc[1][j] = fma2(a0hi, b0, acc[1][j]);
                acc[0][j] = fma2(a1lo, b1, acc[0][j]);
                acc[1][j] = fma2(a1hi, b1, acc[1][j]);
            }
        }
        #pragma unroll
        for (int j = 0; j < 3; j++) {
            int col = tx + 32 * j;
            float bb = b_proj[col];
            #pragma unroll
            for (int r = 0; r < 2; r++) {
                float2 u = unpack2(acc[r][j]);
                qk[(wd * 4 + 2 * r)     * QK_STR + col] = u.x + bb;
                qk[(wd * 4 + 2 * r + 1) * QK_STR + col] = u.y + bb;
            }
        }
    }
    __syncthreads();

    // ---------------- phase 5: scatter to output ----------------
    for (int ch = tid; ch < 96 * 8; ch += TPB) {
        int c = ch >> 3, i = ch & 7;
        const float* s0 = qk + (i * 8) * QK_STR + c;
        float4 a, b;
        a.x = s0[0 * QK_STR]; a.y = s0[1 * QK_STR];
        a.z = s0[2 * QK_STR]; a.w = s0[3 * QK_STR];
        b.x = s0[4 * QK_STR]; b.y = s0[5 * QK_STR];
        b.z = s0[6 * QK_STR]; b.w = s0[7 * QK_STR];
        int dst = c * HWSZ + (hb * 8 + i) * IMG + wb * 8;
        *(float4*)(out + dst) = a;
        *(float4*)(out + dst + 4) = b;
    }
}

extern "C" void kernel_launch(void* const* d_in, const int* in_sizes, int n_in,
                              void* d_out, int out_size)
{
    const float* x         = (const float*)d_in[0];
    const float* rel_table = (const float*)d_in[1];
    const float* w_qkv     = (const float*)d_in[2];
    const float* b_qkv     = (const float*)d_in[3];
    const float* w_proj    = (const float*)d_in[4];
    const float* b_proj    = (const float*)d_in[5];
    float* out = (float*)d_out;

    constexpr int SMEM_BYTES = (6144 + 18688 + 28224 + 1350) * 4;  // 217624
    cudaFuncSetAttribute(swin_fused_kernel,
                         cudaFuncAttributeMaxDynamicSharedMemorySize, SMEM_BYTES);

    swin_fused_kernel<<<4096, TPB, SMEM_BYTES>>>(
        x, rel_table, w_qkv, b_qkv, w_proj, b_proj, out);
}

// round 10
// speedup vs baseline: 1.5935x; 1.1791x over previous
#include <cuda_runtime.h>

// Fused Swin shifted-window attention, one window (64 tokens x 96 ch) per CTA.
// R8: QKV + proj GEMMs via mma.sync.m16n8k8 tf32 with operands stored in
// fragment-permuted smem layouts (conflict-free LDS.128/LDS.64 fragment loads,
// 4x duplication instead of 16x). Attention stays FFMA2 (broadcast loads).

#define TPB 512
typedef unsigned long long u64;

__device__ __forceinline__ u64 pack2(float lo, float hi) {
    u64 r; asm("mov.b64 %0, {%1, %2};" : "=l"(r) : "f"(lo), "f"(hi)); return r;
}
__device__ __forceinline__ float2 unpack2(u64 v) {
    float2 f; asm("mov.b64 {%0, %1}, %2;" : "=f"(f.x), "=f"(f.y) : "l"(v)); return f;
}
__device__ __forceinline__ u64 fma2(u64 a, u64 b, u64 c) {
    u64 d; asm("fma.rn.f32x2 %0, %1, %2, %3;" : "=l"(d) : "l"(a), "l"(b), "l"(c)); return d;
}
__device__ __forceinline__ u64 mul2(u64 a, u64 b) {
    u64 d; asm("mul.rn.f32x2 %0, %1, %2;" : "=l"(d) : "l"(a), "l"(b)); return d;
}
__device__ __forceinline__ u64 add2(u64 a, u64 b) {
    u64 d; asm("add.rn.f32x2 %0, %1, %2;" : "=l"(d) : "l"(a), "l"(b)); return d;
}
__device__ __forceinline__ void f4u(const float4 v, u64& lo, u64& hi) {
    lo = pack2(v.x, v.y); hi = pack2(v.z, v.w);
}
__device__ __forceinline__ float tf32r(float f) {
    unsigned u; asm("cvt.rna.tf32.f32 %0, %1;" : "=r"(u) : "f"(f));
    return __uint_as_float(u);
}
__device__ __forceinline__ void mma_tf32(float c[4], float4 a, float2 b) {
    unsigned a0 = __float_as_uint(a.x), a1 = __float_as_uint(a.y);
    unsigned a2 = __float_as_uint(a.z), a3 = __float_as_uint(a.w);
    unsigned b0 = __float_as_uint(b.x), b1 = __float_as_uint(b.y);
    asm volatile(
        "mma.sync.aligned.m16n8k8.row.col.f32.tf32.tf32.f32 "
        "{%0,%1,%2,%3}, {%4,%5,%6,%7}, {%8,%9}, {%0,%1,%2,%3};"
        : "+f"(c[0]), "+f"(c[1]), "+f"(c[2]), "+f"(c[3])
        : "r"(a0), "r"(a1), "r"(a2), "r"(a3), "r"(b0), "r"(b1));
}

// exp(x), FMA-pipe only. Input y = x*log2(e). rel err ~2e-6.
__device__ __forceinline__ float fast_exp(float y) {
    y = fmaxf(y, -120.0f);
    float t  = y + 12582912.0f;
    float rf = t - 12582912.0f;
    int   k  = __float_as_int(t) - 0x4B400000;
    float f  = y - rf;
    float p  = 1.3333558e-3f;
    p = fmaf(p, f, 9.6181291e-3f);
    p = fmaf(p, f, 5.5504109e-2f);
    p = fmaf(p, f, 2.4022651e-1f);
    p = fmaf(p, f, 6.9314718e-1f);
    p = fmaf(p, f, 1.0f);
    return __int_as_float(__float_as_int(p) + (k << 23));
}

__global__ void __launch_bounds__(TPB, 1)
swin_fused_kernel(const float* __restrict__ x,
                  const float* __restrict__ rel_table,   // (225, 6)
                  const float* __restrict__ w_qkv,       // (288, 96)
                  const float* __restrict__ b_qkv,       // (288)
                  const float* __restrict__ w_proj,      // (96, 96)
                  const float* __restrict__ b_proj,      // (96)
                  float* __restrict__ out)
{
    constexpr int CH   = 96;
    constexpr int IMG  = 512;
    constexpr int HWSZ = IMG * IMG;
    constexpr int CHW  = CH * HWSZ;
    constexpr int WC   = IMG * CH;
    constexpr int ROLLOFF = 4 * WC + 4 * CH;
    constexpr int QK_STR = 292;
    constexpr int SC_STR = 392;
    constexpr float L2E  = 1.4426950408889634f;

    extern __shared__ float sm[];
    float* aperm = sm;                   // 6144: A operand, fragment-permuted
    float* qk    = sm + 6144;            // 18688: qkv tile / proj out (plain)
    float* wsm   = sm + 6144 + 18688;    // 28224: Bperm weights / scores alias
    float* sc    = wsm;
    float* ts    = wsm + 28224;          // 1350: bias table

    const int tid  = threadIdx.x;
    const int lane = tid & 31;
    const int wid  = tid >> 5;
    const int gid  = lane >> 2, tig = lane & 3;
    const int hb   = blockIdx.x >> 6;
    const int wb   = blockIdx.x & 63;

    // ---------------- phase 0: loads ----------------
    for (int i = tid; i < 225 * 6; i += TPB) ts[i] = rel_table[i];
    // w_qkv (288x96) -> Bperm: block (kb, nb): [32][2], idx=((kb*36+nb)*32+l)*2
    for (int i4 = tid * 4; i4 < 288 * 96; i4 += TPB * 4) {
        float4 v = *(const float4*)(w_qkv + i4);
        int n = i4 / 96, k = i4 % 96;
        int kb = k >> 3, half = (k & 7) >> 2;
        float* d = wsm + ((kb * 36 + (n >> 3)) * 32 + (n & 7) * 4) * 2 + half;
        d[0] = tf32r(v.x); d[2] = tf32r(v.y); d[4] = tf32r(v.z); d[6] = tf32r(v.w);
    }
    // gather rolled window -> Aperm (A[m=token][k=channel], fragment-permuted)
    for (int ch = tid; ch < 96 * 8; ch += TPB) {
        int c = ch >> 3, i = ch & 7;
        int f = c * HWSZ + (hb * 8 + i) * IMG + wb * 8;
        int hh = f / WC;
        int ww = (f / CH) & 511;
        int src = f + ROLLOFF;
        if (hh >= IMG - 4) src -= CHW;
        if (ww >= IMG - 4) src -= WC;
        float4 v0 = *(const float4*)(x + src);
        float4 v1 = *(const float4*)(x + src + 4);
        int kb = c >> 3, tg = c & 3, c4 = (c & 7) >> 2;
        float* base = aperm + ((kb * 4 + (i >> 1)) * 32 + tg) * 4 + (i & 1) + 2 * c4;
        base[0 * 16] = tf32r(v0.x); base[1 * 16] = tf32r(v0.y);
        base[2 * 16] = tf32r(v0.z); base[3 * 16] = tf32r(v0.w);
        base[4 * 16] = tf32r(v1.x); base[5 * 16] = tf32r(v1.y);
        base[6 * 16] = tf32r(v1.z); base[7 * 16] = tf32r(v1.w);
    }
    __syncthreads();

    // ------- phase 1: QKV GEMM (64x288, K=96) via tf32 mma -----------------
    {
        const int wr = wid & 3, wc = wid >> 2;   // rows wr*16.., cols wc*72..
        float c[9][4];
        #pragma unroll
        for (int j = 0; j < 9; j++)
            #pragma unroll
            for (int r = 0; r < 4; r++) c[j][r] = 0.f;

        #pragma unroll 4
        for (int kb = 0; kb < 12; kb++) {
            float4 af = *(const float4*)(aperm + ((kb * 4 + wr) * 32 + lane) * 4);
            const float* bp = wsm + (kb * 36 + wc * 9) * 64 + lane * 2;
            #pragma unroll
            for (int j = 0; j < 9; j++) {
                float2 bf = *(const float2*)(bp + j * 64);
                mma_tf32(c[j], af, bf);
            }
        }
        const int row0 = wr * 16 + gid;
        #pragma unroll
        for (int j = 0; j < 9; j++) {
            int col = wc * 72 + j * 8 + tig * 2;
            float2 bb = *(const float2*)(b_qkv + col);
            float2 lo = {c[j][0] + bb.x, c[j][1] + bb.y};
            float2 hi = {c[j][2] + bb.x, c[j][3] + bb.y};
            *(float2*)(qk + row0 * QK_STR + col) = lo;
            *(float2*)(qk + (row0 + 8) * QK_STR + col) = hi;
        }
    }
    __syncthreads();

    // ---------------- phase 2: attention (384 tasks) ----------------
    if (tid < 6 * 64) {
        const bool hl = (hb == 63), wl = (wb == 63);
        const int h = tid >> 6, n = tid & 63;
        const int col = tid;
        const float4* qp = (const float4*)(qk + n * QK_STR + h * 16);
        u64 q2[8];
        {
            float4 a = qp[0], b = qp[1], c = qp[2], d = qp[3];
            f4u(a, q2[0], q2[1]); f4u(b, q2[2], q2[3]);
            f4u(c, q2[4], q2[5]); f4u(d, q2[6], q2[7]);
        }
        const int yi = n >> 3, xi = n & 7;
        const int cn = (hl ? (yi < 4 ? 1 : 2) : 0) * 3
                     + (wl ? (xi < 4 ? 1 : 2) : 0);

        float mx = -1e30f;
        #pragma unroll 2
        for (int m = 0; m < 64; m++) {
            const float4* kp = (const float4*)(qk + m * QK_STR + 96 + h * 16);
            float4 kv0 = kp[0], kv1 = kp[1], kv2 = kp[2], kv3 = kp[3];
            u64 k0, k1, k2, k3, k4, k5, k6, k7;
            f4u(kv0, k0, k1); f4u(kv1, k2, k3);
            f4u(kv2, k4, k5); f4u(kv3, k6, k7);
            u64 da = mul2(q2[0], k0);
            u64 db = mul2(q2[1], k1);
            da = fma2(q2[2], k2, da);
            db = fma2(q2[3], k3, db);
            da = fma2(q2[4], k4, da);
            db = fma2(q2[5], k5, db);
            da = fma2(q2[6], k6, da);
            db = fma2(q2[7], k7, db);
            float2 dd = unpack2(add2(da, db));
            float d = dd.x + dd.y;
            const int ym = m >> 3, xm = m & 7;
            const int idx = (yi - ym + 7) * 15 + (xi - xm + 7);
            float v = d * 0.25f + ts[idx * 6 + h];
            const int cm = (hl ? (ym < 4 ? 1 : 2) : 0) * 3
                         + (wl ? (xm < 4 ? 1 : 2) : 0);
            if (cn != cm) v -= 100.0f;
            sc[m * SC_STR + col] = v;
            mx = fmaxf(mx, v);
        }
        const float mxl = mx * L2E;
        float s0 = 0.f, s1 = 0.f;
        u64 o2[8];
        #pragma unroll
        for (int i = 0; i < 8; i++) o2[i] = 0ull;
        #pragma unroll 2
        for (int m = 0; m < 64; m += 2) {
            float e0 = fast_exp(fmaf(sc[m * SC_STR + col], L2E, -mxl));
            float e1 = fast_exp(fmaf(sc[(m + 1) * SC_STR + col], L2E, -mxl));
            s0 += e0; s1 += e1;
            const u64 p0 = pack2(e0, e0);
            const u64 p1 = pack2(e1, e1);
            const float4* vp0 = (const float4*)(qk + m * QK_STR + 192 + h * 16);
            const float4* vp1 = (const float4*)(qk + (m + 1) * QK_STR + 192 + h * 16);
            float4 va = vp0[0], vb = vp0[1], vc = vp0[2], vd = vp0[3];
            u64 v0, v1, v2, v3, v4, v5, v6, v7;
            f4u(va, v0, v1); f4u(vb, v2, v3); f4u(vc, v4, v5); f4u(vd, v6, v7);
            o2[0] = fma2(p0, v0, o2[0]); o2[1] = fma2(p0, v1, o2[1]);
            o2[2] = fma2(p0, v2, o2[2]); o2[3] = fma2(p0, v3, o2[3]);
            o2[4] = fma2(p0, v4, o2[4]); o2[5] = fma2(p0, v5, o2[5]);
            o2[6] = fma2(p0, v6, o2[6]); o2[7] = fma2(p0, v7, o2[7]);
            va = vp1[0]; vb = vp1[1]; vc = vp1[2]; vd = vp1[3];
            f4u(va, v0, v1); f4u(vb, v2, v3); f4u(vc, v4, v5); f4u(vd, v6, v7);
            o2[0] = fma2(p1, v0, o2[0]); o2[1] = fma2(p1, v1, o2[1]);
            o2[2] = fma2(p1, v2, o2[2]); o2[3] = fma2(p1, v3, o2[3]);
            o2[4] = fma2(p1, v4, o2[4]); o2[5] = fma2(p1, v5, o2[5]);
            o2[6] = fma2(p1, v6, o2[6]); o2[7] = fma2(p1, v7, o2[7]);
        }
        const float inv = 1.0f / (s0 + s1);
        // store attn output to Aperm (A[m=token n][k=channel]) for proj mma
        const int mt = n >> 4, mm = n & 15;
        const int agid = mm & 7, ahi = mm >> 3;
        #pragma unroll
        for (int i = 0; i < 8; i++) {
            float2 u = unpack2(o2[i]);
            int c0 = h * 16 + 2 * i;
            int kb = c0 >> 3, kk = c0 & 7, tg = kk & 3, c4 = kk >> 2;
            float* base = aperm + ((kb * 4 + mt) * 32 + agid * 4 + tg) * 4
                        + ahi + 2 * c4;
            base[0] = tf32r(u.x * inv);
            base[4] = tf32r(u.y * inv);   // tig+1 -> +4
        }
    }
    __syncthreads();

    // ---------------- phase 3: w_proj -> Bperm (overwrites scores) ----------
    for (int i4 = tid * 4; i4 < 96 * 96; i4 += TPB * 4) {
        float4 v = *(const float4*)(w_proj + i4);
        int n = i4 / 96, k = i4 % 96;
        int kb = k >> 3, half = (k & 7) >> 2;
        float* d = wsm + ((kb * 12 + (n >> 3)) * 32 + (n & 7) * 4) * 2 + half;
        d[0] = tf32r(v.x); d[2] = tf32r(v.y); d[4] = tf32r(v.z); d[6] = tf32r(v.w);
    }
    __syncthreads();

    // ------- phase 4: proj GEMM (64x96, K=96) via tf32 mma -----------------
    {
        const int wr = wid & 3, wc = wid >> 2;   // rows wr*16.., cols wc*24..
        float c[3][4];
        #pragma unroll
        for (int j = 0; j < 3; j++)
            #pragma unroll
            for (int r = 0; r < 4; r++) c[j][r] = 0.f;

        #pragma unroll 4
        for (int kb = 0; kb < 12; kb++) {
            float4 af = *(const float4*)(aperm + ((kb * 4 + wr) * 32 + lane) * 4);
            const float* bp = wsm + (kb * 12 + wc * 3) * 64 + lane * 2;
            #pragma unroll
            for (int j = 0; j < 3; j++) {
                float2 bf = *(const float2*)(bp + j * 64);
                mma_tf32(c[j], af, bf);
            }
        }
        const int row0 = wr * 16 + gid;
        #pragma unroll
        for (int j = 0; j < 3; j++) {
            int col = wc * 24 + j * 8 + tig * 2;
            float2 bb = *(const float2*)(b_proj + col);
            float2 lo = {c[j][0] + bb.x, c[j][1] + bb.y};
            float2 hi = {c[j][2] + bb.x, c[j][3] + bb.y};
            *(float2*)(qk + row0 * QK_STR + col) = lo;
            *(float2*)(qk + (row0 + 8) * QK_STR + col) = hi;
        }
    }
    __syncthreads();

    // ---------------- phase 5: scatter to output ----------------
    for (int ch = tid; ch < 96 * 8; ch += TPB) {
        int c = ch >> 3, i = ch & 7;
        const float* s0 = qk + (i * 8) * QK_STR + c;
        float4 a, b;
        a.x = s0[0 * QK_STR]; a.y = s0[1 * QK_STR];
        a.z = s0[2 * QK_STR]; a.w = s0[3 * QK_STR];
        b.x = s0[4 * QK_STR]; b.y = s0[5 * QK_STR];
        b.z = s0[6 * QK_STR]; b.w = s0[7 * QK_STR];
        int dst = c * HWSZ + (hb * 8 + i) * IMG + wb * 8;
        *(float4*)(out + dst) = a;
        *(float4*)(out + dst + 4) = b;
    }
}

extern "C" void kernel_launch(void* const* d_in, const int* in_sizes, int n_in,
                              void* d_out, int out_size)
{
    const float* x         = (const float*)d_in[0];
    const float* rel_table = (const float*)d_in[1];
    const float* w_qkv     = (const float*)d_in[2];
    const float* b_qkv     = (const float*)d_in[3];
    const float* w_proj    = (const float*)d_in[4];
    const float* b_proj    = (const float*)d_in[5];
    float* out = (float*)d_out;

    constexpr int SMEM_BYTES = (6144 + 18688 + 28224 + 1350) * 4;  // 217624
    cudaFuncSetAttribute(swin_fused_kernel,
                         cudaFuncAttributeMaxDynamicSharedMemorySize, SMEM_BYTES);

    swin_fused_kernel<<<4096, TPB, SMEM_BYTES>>>(
        x, rel_table, w_qkv, b_qkv, w_proj, b_proj, out);
}

// round 15
// speedup vs baseline: 2.0920x; 1.3128x over previous
#include <cuda_runtime.h>

// Fused Swin shifted-window attention, one window (64 tokens x 96 ch) per CTA.
// R13: R10 (full tensor-core pipeline) with the P re-fragmentation shuffle
// FIXED: element selection must use the destination lane's tig&1, so shuffle
// both elements from the source lane and select locally (8 shfls per k-tile).

#define TPB 512

__device__ __forceinline__ float tf32r(float f) {
    unsigned u; asm("cvt.rna.tf32.f32 %0, %1;" : "=r"(u) : "f"(f));
    return __uint_as_float(u);
}
__device__ __forceinline__ void mma_tf32(float c[4], const float a[4],
                                         float b0, float b1) {
    asm volatile(
        "mma.sync.aligned.m16n8k8.row.col.f32.tf32.tf32.f32 "
        "{%0,%1,%2,%3}, {%4,%5,%6,%7}, {%8,%9}, {%0,%1,%2,%3};"
        : "+f"(c[0]), "+f"(c[1]), "+f"(c[2]), "+f"(c[3])
        : "r"(__float_as_uint(a[0])), "r"(__float_as_uint(a[1])),
          "r"(__float_as_uint(a[2])), "r"(__float_as_uint(a[3])),
          "r"(__float_as_uint(b0)), "r"(__float_as_uint(b1)));
}

// exp(x), FMA-pipe only. Input y = x*log2(e). rel err ~2e-6.
__device__ __forceinline__ float fast_exp(float y) {
    y = fmaxf(y, -120.0f);
    float t  = y + 12582912.0f;
    float rf = t - 12582912.0f;
    int   k  = __float_as_int(t) - 0x4B400000;
    float f  = y - rf;
    float p  = 1.3333558e-3f;
    p = fmaf(p, f, 9.6181291e-3f);
    p = fmaf(p, f, 5.5504109e-2f);
    p = fmaf(p, f, 2.4022651e-1f);
    p = fmaf(p, f, 6.9314718e-1f);
    p = fmaf(p, f, 1.0f);
    return __int_as_float(__float_as_int(p) + (k << 23));
}

__global__ void __launch_bounds__(TPB, 1)
swin_fused_kernel(const float* __restrict__ x,
                  const float* __restrict__ rel_table,   // (225, 6)
                  const float* __restrict__ w_qkv,       // (288, 96)
                  const float* __restrict__ b_qkv,       // (288)
                  const float* __restrict__ w_proj,      // (96, 96)
                  const float* __restrict__ b_proj,      // (96)
                  float* __restrict__ out)
{
    constexpr int CH   = 96;
    constexpr int IMG  = 512;
    constexpr int HWSZ = IMG * IMG;
    constexpr int CHW  = CH * HWSZ;
    constexpr int WC   = IMG * CH;
    constexpr int ROLLOFF = 4 * WC + 4 * CH;
    constexpr int QK_STR = 292;          // stride mod 32 == 4 (frag loads clean)
    constexpr float L2E  = 1.4426950408889634f;

    extern __shared__ float sm[];
    float* aperm = sm;                   // 6144: A operand, fragment-permuted
    float* qk    = sm + 6144;            // 18688: qkv tile / proj out (plain)
    float* wsm   = sm + 6144 + 18688;    // 28224: Bperm weights
    float* ts    = wsm + 28224;          // 1350: bias table [h][15][15]

    const int tid  = threadIdx.x;
    const int lane = tid & 31;
    const int wid  = tid >> 5;
    const int gid  = lane >> 2, tig = lane & 3;
    const int hb   = blockIdx.x >> 6;
    const int wb   = blockIdx.x & 63;

    // ---------------- phase 0: loads ----------------
    for (int i = tid; i < 225 * 6; i += TPB) {
        int h = i / 225, idx = i - h * 225;
        ts[i] = rel_table[idx * 6 + h];
    }
    // w_qkv (288x96) -> Bperm; fold 0.25 q-scale into rows n<96
    for (int i4 = tid * 4; i4 < 288 * 96; i4 += TPB * 4) {
        float4 v = *(const float4*)(w_qkv + i4);
        int n = i4 / 96, k = i4 % 96;
        if (n < 96) { v.x *= 0.25f; v.y *= 0.25f; v.z *= 0.25f; v.w *= 0.25f; }
        int kb = k >> 3, half = (k & 7) >> 2;
        float* d = wsm + ((kb * 36 + (n >> 3)) * 32 + (n & 7) * 4) * 2 + half;
        d[0] = tf32r(v.x); d[2] = tf32r(v.y); d[4] = tf32r(v.z); d[6] = tf32r(v.w);
    }
    // gather rolled window -> Aperm
    for (int ch = tid; ch < 96 * 8; ch += TPB) {
        int c = ch >> 3, i = ch & 7;
        int f = c * HWSZ + (hb * 8 + i) * IMG + wb * 8;
        int hh = f / WC;
        int ww = (f / CH) & 511;
        int src = f + ROLLOFF;
        if (hh >= IMG - 4) src -= CHW;
        if (ww >= IMG - 4) src -= WC;
        float4 v0 = *(const float4*)(x + src);
        float4 v1 = *(const float4*)(x + src + 4);
        int kb = c >> 3, tg = c & 3, c4 = (c & 7) >> 2;
        float* base = aperm + ((kb * 4 + (i >> 1)) * 32 + tg) * 4 + (i & 1) + 2 * c4;
        base[0 * 16] = tf32r(v0.x); base[1 * 16] = tf32r(v0.y);
        base[2 * 16] = tf32r(v0.z); base[3 * 16] = tf32r(v0.w);
        base[4 * 16] = tf32r(v1.x); base[5 * 16] = tf32r(v1.y);
        base[6 * 16] = tf32r(v1.z); base[7 * 16] = tf32r(v1.w);
    }
    __syncthreads();

    // ------- phase 1: QKV GEMM (64x288, K=96) via tf32 mma -----------------
    {
        const int wr = wid & 3, wc = wid >> 2;
        float c[9][4];
        #pragma unroll
        for (int j = 0; j < 9; j++)
            #pragma unroll
            for (int r = 0; r < 4; r++) c[j][r] = 0.f;

        #pragma unroll 4
        for (int kb = 0; kb < 12; kb++) {
            float4 af = *(const float4*)(aperm + ((kb * 4 + wr) * 32 + lane) * 4);
            const float a[4] = {af.x, af.y, af.z, af.w};
            const float* bp = wsm + (kb * 36 + wc * 9) * 64 + lane * 2;
            #pragma unroll
            for (int j = 0; j < 9; j++) {
                float2 bf = *(const float2*)(bp + j * 64);
                mma_tf32(c[j], a, bf.x, bf.y);
            }
        }
        const int row0 = wr * 16 + gid;
        #pragma unroll
        for (int j = 0; j < 9; j++) {
            int col = wc * 72 + j * 8 + tig * 2;
            float2 bb = *(const float2*)(b_qkv + col);
            if (col < 96) { bb.x *= 0.25f; bb.y *= 0.25f; }   // q bias scale
            float2 lo = {tf32r(c[j][0] + bb.x), tf32r(c[j][1] + bb.y)};
            float2 hi = {tf32r(c[j][2] + bb.x), tf32r(c[j][3] + bb.y)};
            *(float2*)(qk + row0 * QK_STR + col) = lo;
            *(float2*)(qk + (row0 + 8) * QK_STR + col) = hi;
        }
    }
    __syncthreads();

    // -------- phase 2a: w_proj -> Bperm (overlaps with attention) ----------
    for (int i4 = tid * 4; i4 < 96 * 96; i4 += TPB * 4) {
        float4 v = *(const float4*)(w_proj + i4);
        int n = i4 / 96, k = i4 % 96;
        int kb = k >> 3, half = (k & 7) >> 2;
        float* d = wsm + ((kb * 12 + (n >> 3)) * 32 + (n & 7) * 4) * 2 + half;
        d[0] = tf32r(v.x); d[2] = tf32r(v.y); d[4] = tf32r(v.z); d[6] = tf32r(v.w);
    }

    // -------- phase 2b: attention, 24 slabs = (head, 16-row block) ---------
    {
        const bool hl = (hb == 63), wl = (wb == 63);
        const int nsl = (wid < 8) ? 2 : 1;
        for (int it = 0; it < nsl; it++) {
            const int s  = it ? (16 + wid) : wid;
            const int h  = s >> 2, rb = s & 3;

            // Q a-frags (16 rows x 16 dims, 2 k-chunks)
            float qa[2][4];
            #pragma unroll
            for (int kc = 0; kc < 2; kc++) {
                int r0 = (16 * rb + gid) * QK_STR + h * 16 + 8 * kc + tig;
                qa[kc][0] = qk[r0];
                qa[kc][1] = qk[r0 + 8 * QK_STR];
                qa[kc][2] = qk[r0 + 4];
                qa[kc][3] = qk[r0 + 8 * QK_STR + 4];
            }

            // S = Q @ K^T + bias (+ mask on boundary windows)
            float c[8][4];
            const float* th = ts + h * 225;
            #pragma unroll
            for (int j = 0; j < 8; j++) {
                c[j][0] = c[j][1] = c[j][2] = c[j][3] = 0.f;
                #pragma unroll
                for (int kc = 0; kc < 2; kc++) {
                    int kb0 = (8 * j + gid) * QK_STR + 96 + h * 16 + 8 * kc + tig;
                    mma_tf32(c[j], qa[kc], qk[kb0], qk[kb0 + 4]);
                }
                int dy = 2 * rb - j + 7;
                int dx = gid - 2 * tig + 7;
                c[j][0] += th[dy * 15 + dx];
                c[j][1] += th[dy * 15 + dx - 1];
                c[j][2] += th[(dy + 1) * 15 + dx];
                c[j][3] += th[(dy + 1) * 15 + dx - 1];
            }
            if (hl | wl) {
                int cyA = hl ? ((2 * rb) < 4 ? 1 : 2) : 0;
                int cyB = hl ? ((2 * rb + 1) < 4 ? 1 : 2) : 0;
                int cx  = wl ? (gid < 4 ? 1 : 2) : 0;
                int cnA = cyA * 3 + cx, cnB = cyB * 3 + cx;
                int cmx0 = wl ? ((2 * tig) < 4 ? 1 : 2) : 0;
                int cmx1 = wl ? ((2 * tig + 1) < 4 ? 1 : 2) : 0;
                #pragma unroll
                for (int j = 0; j < 8; j++) {
                    int cmy = hl ? (j < 4 ? 1 : 2) : 0;
                    int cm0 = cmy * 3 + cmx0, cm1 = cmy * 3 + cmx1;
                    if (cnA != cm0) c[j][0] -= 100.f;
                    if (cnA != cm1) c[j][1] -= 100.f;
                    if (cnB != cm0) c[j][2] -= 100.f;
                    if (cnB != cm1) c[j][3] -= 100.f;
                }
            }

            // row max over the 4-lane row group
            float mA = -1e30f, mB = -1e30f;
            #pragma unroll
            for (int j = 0; j < 8; j++) {
                mA = fmaxf(mA, fmaxf(c[j][0], c[j][1]));
                mB = fmaxf(mB, fmaxf(c[j][2], c[j][3]));
            }
            mA = fmaxf(mA, __shfl_xor_sync(0xffffffffu, mA, 1));
            mA = fmaxf(mA, __shfl_xor_sync(0xffffffffu, mA, 2));
            mB = fmaxf(mB, __shfl_xor_sync(0xffffffffu, mB, 1));
            mB = fmaxf(mB, __shfl_xor_sync(0xffffffffu, mB, 2));
            const float mAl = mA * L2E, mBl = mB * L2E;

            // exp (tf32-rounded so P frags are mma-ready) + row sums
            float sA = 0.f, sB = 0.f;
            #pragma unroll
            for (int j = 0; j < 8; j++) {
                float e0 = tf32r(fast_exp(fmaf(c[j][0], L2E, -mAl)));
                float e1 = tf32r(fast_exp(fmaf(c[j][1], L2E, -mAl)));
                float e2 = tf32r(fast_exp(fmaf(c[j][2], L2E, -mBl)));
                float e3 = tf32r(fast_exp(fmaf(c[j][3], L2E, -mBl)));
                c[j][0] = e0; c[j][1] = e1; c[j][2] = e2; c[j][3] = e3;
                sA += e0 + e1; sB += e2 + e3;
            }
            sA += __shfl_xor_sync(0xffffffffu, sA, 1);
            sA += __shfl_xor_sync(0xffffffffu, sA, 2);
            sB += __shfl_xor_sync(0xffffffffu, sB, 1);
            sB += __shfl_xor_sync(0xffffffffu, sB, 2);

            // O = P @ V (unnormalized). P re-fragment: dest (gid,tig) needs
            // P[gid(+8)][8j+tig(+4)], held by lane 4*gid+(tig>>1) (+2) in
            // element index (tig&1). Shuffle BOTH elements, select locally.
            float o[2][4];
            o[0][0]=o[0][1]=o[0][2]=o[0][3]=0.f;
            o[1][0]=o[1][1]=o[1][2]=o[1][3]=0.f;
            const int src = (gid << 2) | (tig >> 1);
            const bool odd = (tig & 1);
            #pragma unroll
            for (int j = 0; j < 8; j++) {
                float u0 = __shfl_sync(0xffffffffu, c[j][0], src);
                float u1 = __shfl_sync(0xffffffffu, c[j][1], src);
                float u2 = __shfl_sync(0xffffffffu, c[j][0], src + 2);
                float u3 = __shfl_sync(0xffffffffu, c[j][1], src + 2);
                float w0 = __shfl_sync(0xffffffffu, c[j][2], src);
                float w1 = __shfl_sync(0xffffffffu, c[j][3], src);
                float w2 = __shfl_sync(0xffffffffu, c[j][2], src + 2);
                float w3 = __shfl_sync(0xffffffffu, c[j][3], src + 2);
                float pa[4];
                pa[0] = odd ? u1 : u0;
                pa[2] = odd ? u3 : u2;
                pa[1] = odd ? w1 : w0;
                pa[3] = odd ? w3 : w2;
                #pragma unroll
                for (int nt = 0; nt < 2; nt++) {
                    int vb = (8 * j + tig) * QK_STR + 192 + h * 16 + 8 * nt + gid;
                    mma_tf32(o[nt], pa, qk[vb], qk[vb + 4 * QK_STR]);
                }
            }

            // normalize + store to Aperm (proj A fragment layout)
            const float iA = __fdividef(1.f, sA), iB = __fdividef(1.f, sB);
            #pragma unroll
            for (int nt = 0; nt < 2; nt++) {
                int ch0 = h * 16 + 8 * nt + 2 * tig;          // and ch0+1
                int kb = ch0 >> 3;
                int tg0 = ch0 & 3, c40 = (ch0 & 7) >> 2;
                int tg1 = (ch0 + 1) & 3, c41 = ((ch0 + 1) & 7) >> 2;
                int base = ((kb * 4 + rb) * 32 + gid * 4) * 4;
                aperm[base + tg0 * 4 + 2 * c40]     = tf32r(o[nt][0] * iA);
                aperm[base + tg1 * 4 + 2 * c41]     = tf32r(o[nt][1] * iA);
                aperm[base + tg0 * 4 + 2 * c40 + 1] = tf32r(o[nt][2] * iB);
                aperm[base + tg1 * 4 + 2 * c41 + 1] = tf32r(o[nt][3] * iB);
            }
        }
    }
    __syncthreads();

    // ------- phase 4: proj GEMM (64x96, K=96) via tf32 mma -----------------
    {
        const int wr = wid & 3, wc = wid >> 2;
        float c[3][4];
        #pragma unroll
        for (int j = 0; j < 3; j++)
            #pragma unroll
            for (int r = 0; r < 4; r++) c[j][r] = 0.f;

        #pragma unroll 4
        for (int kb = 0; kb < 12; kb++) {
            float4 af = *(const float4*)(aperm + ((kb * 4 + wr) * 32 + lane) * 4);
            const float a[4] = {af.x, af.y, af.z, af.w};
            const float* bp = wsm + (kb * 12 + wc * 3) * 64 + lane * 2;
            #pragma unroll
            for (int j = 0; j < 3; j++) {
                float2 bf = *(const float2*)(bp + j * 64);
                mma_tf32(c[j], a, bf.x, bf.y);
            }
        }
        const int row0 = wr * 16 + gid;
        #pragma unroll
        for (int j = 0; j < 3; j++) {
            int col = wc * 24 + j * 8 + tig * 2;
            float2 bb = *(const float2*)(b_proj + col);
            float2 lo = {c[j][0] + bb.x, c[j][1] + bb.y};
            float2 hi = {c[j][2] + bb.x, c[j][3] + bb.y};
            *(float2*)(qk + row0 * QK_STR + col) = lo;
            *(float2*)(qk + (row0 + 8) * QK_STR + col) = hi;
        }
    }
    __syncthreads();

    // ---------------- phase 5: scatter to output ----------------
    for (int ch = tid; ch < 96 * 8; ch += TPB) {
        int c = ch >> 3, i = ch & 7;
        const float* s0 = qk + (i * 8) * QK_STR + c;
        float4 a, b;
        a.x = s0[0 * QK_STR]; a.y = s0[1 * QK_STR];
        a.z = s0[2 * QK_STR]; a.w = s0[3 * QK_STR];
        b.x = s0[4 * QK_STR]; b.y = s0[5 * QK_STR];
        b.z = s0[6 * QK_STR]; b.w = s0[7 * QK_STR];
        int dst = c * HWSZ + (hb * 8 + i) * IMG + wb * 8;
        *(float4*)(out + dst) = a;
        *(float4*)(out + dst + 4) = b;
    }
}

extern "C" void kernel_launch(void* const* d_in, const int* in_sizes, int n_in,
                              void* d_out, int out_size)
{
    const float* x         = (const float*)d_in[0];
    const float* rel_table = (const float*)d_in[1];
    const float* w_qkv     = (const float*)d_in[2];
    const float* b_qkv     = (const float*)d_in[3];
    const float* w_proj    = (const float*)d_in[4];
    const float* b_proj    = (const float*)d_in[5];
    float* out = (float*)d_out;

    constexpr int SMEM_BYTES = (6144 + 18688 + 28224 + 1350) * 4;  // 217624
    cudaFuncSetAttribute(swin_fused_kernel,
                         cudaFuncAttributeMaxDynamicSharedMemorySize, SMEM_BYTES);

    swin_fused_kernel<<<4096, TPB, SMEM_BYTES>>>(
        x, rel_table, w_qkv, b_qkv, w_proj, b_proj, out);
}